// round 1
// baseline (speedup 1.0000x reference)
#include <cuda_runtime.h>
#include <cuda_bf16.h>
#include <math.h>

// ---------------- problem constants ----------------
#define L_SEQ   4096
#define IDIM    2048
#define NHEADS  8
#define NGROUPS 2
#define HDIM    256
#define ROPED   64
#define ODIM    (NHEADS*HDIM)     // 2048
#define NKV     (NGROUPS*HDIM)    // 512
#define QSCALE  0.0625f           // 256^-0.5

// ---------------- scratch (device globals; no allocs allowed) ----------------
__device__ float g_qraw[(size_t)L_SEQ * (ODIM*2)];   // 64 MB  (L, 4096)
__device__ float g_q   [(size_t)L_SEQ * ODIM];       // 32 MB  (L, 8, 256) normed+rope'd
__device__ float g_gate[(size_t)L_SEQ * ODIM];       // 32 MB  (L, 2048) raw gate
__device__ float g_kraw[(size_t)L_SEQ * NKV];        // 8 MB
__device__ float g_k   [(size_t)L_SEQ * NKV];        // 8 MB   (L, 2, 256) normed+rope'd
__device__ float g_v   [(size_t)L_SEQ * NKV];        // 8 MB   (L, 2, 256)
__device__ float g_att [(size_t)L_SEQ * ODIM];       // 32 MB  gated attention output

// ---------------- SGEMM: C(MxN) = A(MxK) @ B(KxN), row-major ----------------
// 128x128 tile, BK=16, 256 threads, 8x8 per-thread tile.
__global__ __launch_bounds__(256) void sgemm128(
    const float* __restrict__ A, const float* __restrict__ B,
    float* __restrict__ C, int M, int N, int K)
{
    __shared__ float As[16][132];   // transposed A tile, padded
    __shared__ float Bs[16][128];

    const int tid  = threadIdx.x;
    const int row0 = blockIdx.y * 128;
    const int col0 = blockIdx.x * 128;
    const int ty   = tid >> 4;      // 0..15
    const int tx   = tid & 15;      // 0..15

    float acc[8][8];
#pragma unroll
    for (int i = 0; i < 8; i++)
#pragma unroll
        for (int j = 0; j < 8; j++) acc[i][j] = 0.0f;

    for (int k0 = 0; k0 < K; k0 += 16) {
#pragma unroll
        for (int p = 0; p < 2; p++) {
            int f  = tid + p * 256;          // 0..511
            int ar = f >> 2;                 // 0..127
            int ac = (f & 3) * 4;            // 0,4,8,12
            float4 a = *reinterpret_cast<const float4*>(&A[(size_t)(row0 + ar) * K + k0 + ac]);
            As[ac + 0][ar] = a.x; As[ac + 1][ar] = a.y;
            As[ac + 2][ar] = a.z; As[ac + 3][ar] = a.w;
            int br = f >> 5;                 // 0..15
            int bc = (f & 31) * 4;           // 0..124
            *reinterpret_cast<float4*>(&Bs[br][bc]) =
                *reinterpret_cast<const float4*>(&B[(size_t)(k0 + br) * N + col0 + bc]);
        }
        __syncthreads();
#pragma unroll
        for (int k = 0; k < 16; k++) {
            float4 a0 = *reinterpret_cast<const float4*>(&As[k][ty * 8]);
            float4 a1 = *reinterpret_cast<const float4*>(&As[k][ty * 8 + 4]);
            float4 b0 = *reinterpret_cast<const float4*>(&Bs[k][tx * 8]);
            float4 b1 = *reinterpret_cast<const float4*>(&Bs[k][tx * 8 + 4]);
            float ra[8] = {a0.x,a0.y,a0.z,a0.w,a1.x,a1.y,a1.z,a1.w};
            float rb[8] = {b0.x,b0.y,b0.z,b0.w,b1.x,b1.y,b1.z,b1.w};
#pragma unroll
            for (int i = 0; i < 8; i++)
#pragma unroll
                for (int j = 0; j < 8; j++) acc[i][j] += ra[i] * rb[j];
        }
        __syncthreads();
    }

#pragma unroll
    for (int i = 0; i < 8; i++) {
        float* crow = &C[(size_t)(row0 + ty * 8 + i) * N + col0 + tx * 8];
        float4 v0 = make_float4(acc[i][0], acc[i][1], acc[i][2], acc[i][3]);
        float4 v1 = make_float4(acc[i][4], acc[i][5], acc[i][6], acc[i][7]);
        *reinterpret_cast<float4*>(&crow[0]) = v0;
        *reinterpret_cast<float4*>(&crow[4]) = v1;
    }
}

// ---------------- RMSNorm + partial RoPE for Q (+ gate extraction) ----------------
// grid (L, 8), 256 threads; qraw row layout: col = h*512 + j (j<256 -> q, j>=256 -> gate)
__global__ __launch_bounds__(256) void qnorm_rope_kernel(
    const float* __restrict__ cosb, const float* __restrict__ sinb,
    const float* __restrict__ gamma)
{
    const int l = blockIdx.x;
    const int h = blockIdx.y;
    const int d = threadIdx.x;
    const float* row = g_qraw + (size_t)l * (ODIM * 2) + h * 512;
    float v  = row[d];
    float gv = row[256 + d];

    float s = v * v;
#pragma unroll
    for (int o = 16; o > 0; o >>= 1) s += __shfl_xor_sync(0xffffffffu, s, o);
    __shared__ float wsum[8];
    __shared__ float sh[256];
    if ((d & 31) == 0) wsum[d >> 5] = s;
    __syncthreads();
    float tot = 0.0f;
#pragma unroll
    for (int w = 0; w < 8; w++) tot += wsum[w];
    float rstd = rsqrtf(tot * (1.0f / 256.0f) + 1e-6f);
    float y = v * rstd * gamma[d];
    sh[d] = y;
    __syncthreads();
    float out = y;
    if (d < ROPED) {
        float rot = (d < ROPED / 2) ? -sh[d + ROPED / 2] : sh[d - ROPED / 2];
        out = y * cosb[(size_t)l * ROPED + d] + rot * sinb[(size_t)l * ROPED + d];
    }
    g_q   [(size_t)l * ODIM + h * HDIM + d] = out;
    g_gate[(size_t)l * ODIM + h * HDIM + d] = gv;
}

// ---------------- RMSNorm + partial RoPE for K ----------------
// grid (L, 2), 256 threads
__global__ __launch_bounds__(256) void knorm_rope_kernel(
    const float* __restrict__ cosb, const float* __restrict__ sinb,
    const float* __restrict__ gamma)
{
    const int l = blockIdx.x;
    const int g = blockIdx.y;
    const int d = threadIdx.x;
    float v = g_kraw[(size_t)l * NKV + g * HDIM + d];

    float s = v * v;
#pragma unroll
    for (int o = 16; o > 0; o >>= 1) s += __shfl_xor_sync(0xffffffffu, s, o);
    __shared__ float wsum[8];
    __shared__ float sh[256];
    if ((d & 31) == 0) wsum[d >> 5] = s;
    __syncthreads();
    float tot = 0.0f;
#pragma unroll
    for (int w = 0; w < 8; w++) tot += wsum[w];
    float rstd = rsqrtf(tot * (1.0f / 256.0f) + 1e-6f);
    float y = v * rstd * gamma[d];
    sh[d] = y;
    __syncthreads();
    float out = y;
    if (d < ROPED) {
        float rot = (d < ROPED / 2) ? -sh[d + ROPED / 2] : sh[d - ROPED / 2];
        out = y * cosb[(size_t)l * ROPED + d] + rot * sinb[(size_t)l * ROPED + d];
    }
    g_k[(size_t)l * NKV + g * HDIM + d] = out;
}

// ---------------- Flash attention, fp32, Br=Bc=64, D=256 ----------------
#define BR 64
#define BC 64
#define SS_STRIDE 68

__global__ __launch_bounds__(256, 1) void attn_kernel()
{
    extern __shared__ float smem[];
    float* Qst  = smem;                       // [256][64], k-major, pre-scaled
    float* Kst  = Qst + 256 * 64;             // [256][64], k-major
    float* Vs   = Kst + 256 * 64;             // [64][256], row-major
    float* Ss   = Vs  + 64 * 256;             // [64][68]   scores / probs
    float* mrow = Ss  + 64 * SS_STRIDE;       // [64]
    float* lrow = mrow + 64;                  // [64]
    float* crow = lrow + 64;                  // [64]

    const int tid = threadIdx.x;
    const int qt  = gridDim.x - 1 - blockIdx.x;   // big tiles first
    const int h   = blockIdx.y;
    const int g   = h >> 2;                       // GROUP_SIZE = 4
    const int i0  = qt * BR;

    // ---- load Q tile transposed + scaled ----
    {
        const int j   = tid >> 2;       // 0..63 (query row within tile)
        const int c4b = tid & 3;
#pragma unroll
        for (int p = 0; p < 16; p++) {
            int c4 = c4b + 4 * p;       // 0..63 (float4 index along D)
            float4 a = *reinterpret_cast<const float4*>(
                &g_q[((size_t)(i0 + j) * NHEADS + h) * HDIM + c4 * 4]);
            Qst[(c4 * 4 + 0) * 64 + j] = a.x * QSCALE;
            Qst[(c4 * 4 + 1) * 64 + j] = a.y * QSCALE;
            Qst[(c4 * 4 + 2) * 64 + j] = a.z * QSCALE;
            Qst[(c4 * 4 + 3) * 64 + j] = a.w * QSCALE;
        }
    }
    if (tid < 64) { mrow[tid] = -INFINITY; lrow[tid] = 0.0f; }

    const int oty = tid >> 5;   // 0..7  (row group for O)
    const int otx = tid & 31;   // 0..31 (dim group for O)
    float oacc[8][8];
#pragma unroll
    for (int i = 0; i < 8; i++)
#pragma unroll
        for (int jj = 0; jj < 8; jj++) oacc[i][jj] = 0.0f;

    const int sty = tid >> 4;   // 0..15 (row group for S)
    const int stx = tid & 15;   // 0..15 (col group for S)

    for (int j0 = 0; j0 <= i0; j0 += BC) {
        __syncthreads();   // protect Kst/Vs/Ss reuse from previous iteration

        // ---- load K transposed ----
        {
            const int j   = tid >> 2;
            const int c4b = tid & 3;
#pragma unroll
            for (int p = 0; p < 16; p++) {
                int c4 = c4b + 4 * p;
                float4 a = *reinterpret_cast<const float4*>(
                    &g_k[((size_t)(j0 + j) * NGROUPS + g) * HDIM + c4 * 4]);
                Kst[(c4 * 4 + 0) * 64 + j] = a.x;
                Kst[(c4 * 4 + 1) * 64 + j] = a.y;
                Kst[(c4 * 4 + 2) * 64 + j] = a.z;
                Kst[(c4 * 4 + 3) * 64 + j] = a.w;
            }
        }
        // ---- load V row-major ----
        {
#pragma unroll
            for (int p = 0; p < 16; p++) {
                int f  = tid + 256 * p;
                int r  = f >> 6;
                int c4 = f & 63;
                *reinterpret_cast<float4*>(&Vs[r * 256 + c4 * 4]) =
                    *reinterpret_cast<const float4*>(
                        &g_v[((size_t)(j0 + r) * NGROUPS + g) * HDIM + c4 * 4]);
            }
        }
        __syncthreads();

        // ---- S = Q @ K^T  (64x64, 4x4 per-thread tiles, k-outer-product) ----
        float sacc[4][4];
#pragma unroll
        for (int i = 0; i < 4; i++)
#pragma unroll
            for (int j = 0; j < 4; j++) sacc[i][j] = 0.0f;

        const float* qp = &Qst[sty * 4];
        const float* kp = &Kst[stx * 4];
#pragma unroll 8
        for (int k = 0; k < 256; k++) {
            float4 qa = *reinterpret_cast<const float4*>(qp + k * 64);
            float4 kb = *reinterpret_cast<const float4*>(kp + k * 64);
            float qv[4] = {qa.x, qa.y, qa.z, qa.w};
            float kv[4] = {kb.x, kb.y, kb.z, kb.w};
#pragma unroll
            for (int i = 0; i < 4; i++)
#pragma unroll
                for (int j = 0; j < 4; j++) sacc[i][j] += qv[i] * kv[j];
        }
#pragma unroll
        for (int i = 0; i < 4; i++) {
            int r = sty * 4 + i;
#pragma unroll
            for (int j = 0; j < 4; j++) {
                int c = stx * 4 + j;
                float sv = sacc[i][j];
                if (j0 + c > i0 + r) sv = -INFINITY;   // causal mask
                Ss[r * SS_STRIDE + c] = sv;
            }
        }
        __syncthreads();

        // ---- online softmax (one thread per row) ----
        if (tid < 64) {
            const int r = tid;
            float mold = mrow[r];
            float mnew = mold;
#pragma unroll 8
            for (int c = 0; c < 64; c++) mnew = fmaxf(mnew, Ss[r * SS_STRIDE + c]);
            float corr = __expf(mold - mnew);
            float lsum = lrow[r] * corr;
#pragma unroll 8
            for (int c = 0; c < 64; c++) {
                float pv = __expf(Ss[r * SS_STRIDE + c] - mnew);
                Ss[r * SS_STRIDE + c] = pv;
                lsum += pv;
            }
            mrow[r] = mnew; lrow[r] = lsum; crow[r] = corr;
        }
        __syncthreads();

        // ---- O = O*corr + P @ V  (64x256, 8x8 per-thread) ----
#pragma unroll
        for (int i = 0; i < 8; i++) {
            float c = crow[oty * 8 + i];
#pragma unroll
            for (int jj = 0; jj < 8; jj++) oacc[i][jj] *= c;
        }
#pragma unroll 2
        for (int j = 0; j < 64; j++) {
            float4 v0 = *reinterpret_cast<const float4*>(&Vs[j * 256 + otx * 8]);
            float4 v1 = *reinterpret_cast<const float4*>(&Vs[j * 256 + otx * 8 + 4]);
#pragma unroll
            for (int i = 0; i < 8; i++) {
                float pv = Ss[(oty * 8 + i) * SS_STRIDE + j];
                oacc[i][0] += pv * v0.x; oacc[i][1] += pv * v0.y;
                oacc[i][2] += pv * v0.z; oacc[i][3] += pv * v0.w;
                oacc[i][4] += pv * v1.x; oacc[i][5] += pv * v1.y;
                oacc[i][6] += pv * v1.z; oacc[i][7] += pv * v1.w;
            }
        }
    }

    // ---- epilogue: 1/l, sigmoid gate, write g_att ----
#pragma unroll
    for (int i = 0; i < 8; i++) {
        int r = oty * 8 + i;
        float linv = 1.0f / lrow[r];
        size_t base = (size_t)(i0 + r) * ODIM + h * HDIM + otx * 8;
        float4 g0 = *reinterpret_cast<const float4*>(&g_gate[base]);
        float4 g1 = *reinterpret_cast<const float4*>(&g_gate[base + 4]);
        float gv[8] = {g0.x, g0.y, g0.z, g0.w, g1.x, g1.y, g1.z, g1.w};
        float res[8];
#pragma unroll
        for (int jj = 0; jj < 8; jj++) {
            float sig = 1.0f / (1.0f + __expf(-gv[jj]));
            res[jj] = oacc[i][jj] * linv * sig;
        }
        *reinterpret_cast<float4*>(&g_att[base])     = make_float4(res[0], res[1], res[2], res[3]);
        *reinterpret_cast<float4*>(&g_att[base + 4]) = make_float4(res[4], res[5], res[6], res[7]);
    }
}

// ---------------- launch ----------------
extern "C" void kernel_launch(void* const* d_in, const int* in_sizes, int n_in,
                              void* d_out, int out_size)
{
    const float* x    = (const float*)d_in[0];
    const float* cosb = (const float*)d_in[1];
    const float* sinb = (const float*)d_in[2];
    // d_in[3] = mask (ignored; causal mask is implicit)
    const float* wq   = (const float*)d_in[4];
    const float* wk   = (const float*)d_in[5];
    const float* wv   = (const float*)d_in[6];
    const float* wo   = (const float*)d_in[7];
    const float* qg   = (const float*)d_in[8];
    const float* kg   = (const float*)d_in[9];
    float* out        = (float*)d_out;

    float *p_qraw, *p_kraw, *p_v, *p_att;
    cudaGetSymbolAddress((void**)&p_qraw, g_qraw);
    cudaGetSymbolAddress((void**)&p_kraw, g_kraw);
    cudaGetSymbolAddress((void**)&p_v,    g_v);
    cudaGetSymbolAddress((void**)&p_att,  g_att);

    // 1) projections
    sgemm128<<<dim3((ODIM * 2) / 128, L_SEQ / 128), 256>>>(x, wq, p_qraw, L_SEQ, ODIM * 2, IDIM);
    sgemm128<<<dim3(NKV / 128,        L_SEQ / 128), 256>>>(x, wk, p_kraw, L_SEQ, NKV, IDIM);
    sgemm128<<<dim3(NKV / 128,        L_SEQ / 128), 256>>>(x, wv, p_v,    L_SEQ, NKV, IDIM);

    // 2) RMSNorm + RoPE (+ gate split)
    qnorm_rope_kernel<<<dim3(L_SEQ, NHEADS), 256>>>(cosb, sinb, qg);
    knorm_rope_kernel<<<dim3(L_SEQ, NGROUPS), 256>>>(cosb, sinb, kg);

    // 3) causal flash attention + gating
    const int attn_smem = (256 * 64 * 2 + 64 * 256 + 64 * SS_STRIDE + 3 * 64) * sizeof(float);
    cudaFuncSetAttribute(attn_kernel, cudaFuncAttributeMaxDynamicSharedMemorySize, attn_smem);
    attn_kernel<<<dim3(L_SEQ / BR, NHEADS), 256, attn_smem>>>();

    // 4) output projection
    sgemm128<<<dim3(IDIM / 128, L_SEQ / 128), 256>>>(p_att, wo, out, L_SEQ, IDIM, ODIM);
}

// round 3
// speedup vs baseline: 1.3882x; 1.3882x over previous
#include <cuda_runtime.h>
#include <cuda_bf16.h>
#include <math.h>
#include <stdint.h>

// ---------------- problem constants ----------------
#define L_SEQ   4096
#define IDIM    2048
#define NHEADS  8
#define NGROUPS 2
#define HDIM    256
#define ROPED   64
#define ODIM    (NHEADS*HDIM)     // 2048
#define NKV     (NGROUPS*HDIM)    // 512
#define QSCALE  0.0625f           // 256^-0.5

// ---------------- warp-MMA helpers (standard PTX, sm_80+) ----------------
__device__ __forceinline__ void ldsm_x4(uint32_t* r, uint32_t addr) {
    asm volatile("ldmatrix.sync.aligned.m8n8.x4.shared.b16 {%0,%1,%2,%3}, [%4];"
        : "=r"(r[0]), "=r"(r[1]), "=r"(r[2]), "=r"(r[3]) : "r"(addr));
}
__device__ __forceinline__ void mma16816(float* d, const uint32_t* a, uint32_t b0, uint32_t b1) {
    asm volatile("mma.sync.aligned.m16n8k16.row.col.f32.bf16.bf16.f32 "
        "{%0,%1,%2,%3}, {%4,%5,%6,%7}, {%8,%9}, {%0,%1,%2,%3};"
        : "+f"(d[0]), "+f"(d[1]), "+f"(d[2]), "+f"(d[3])
        : "r"(a[0]), "r"(a[1]), "r"(a[2]), "r"(a[3]), "r"(b0), "r"(b1));
}
__device__ __forceinline__ void cp_async16(uint32_t dst, const void* src) {
    asm volatile("cp.async.cg.shared.global [%0], [%1], 16;" :: "r"(dst), "l"(src));
}
#define CP_COMMIT() asm volatile("cp.async.commit_group;" ::: "memory")
#define CP_WAIT1()  asm volatile("cp.async.wait_group 1;" ::: "memory")
#define CP_WAIT0()  asm volatile("cp.async.wait_group 0;" ::: "memory")

__device__ __forceinline__ uint32_t smem_to_u32(const void* p) {
    uint32_t a;
    asm("{ .reg .u64 t; cvta.to.shared.u64 t, %1; cvt.u32.u64 %0, t; }" : "=r"(a) : "l"(p));
    return a;
}

// ---------------- scratch (device globals) ----------------
__device__ float g_qraw[(size_t)L_SEQ * (ODIM*2)];
__device__ float g_q   [(size_t)L_SEQ * ODIM];
__device__ float g_gate[(size_t)L_SEQ * ODIM];
__device__ float g_kraw[(size_t)L_SEQ * NKV];
__device__ float g_k   [(size_t)L_SEQ * NKV];
__device__ float g_v   [(size_t)L_SEQ * NKV];
__device__ float g_att [(size_t)L_SEQ * ODIM];

// split bf16 operands (all GEMMs K = 2048)
__device__ __nv_bfloat16 g_xh [(size_t)L_SEQ * IDIM];
__device__ __nv_bfloat16 g_xl [(size_t)L_SEQ * IDIM];
__device__ __nv_bfloat16 g_wqh[(size_t)(ODIM*2) * IDIM];
__device__ __nv_bfloat16 g_wql[(size_t)(ODIM*2) * IDIM];
__device__ __nv_bfloat16 g_wkh[(size_t)NKV * IDIM];
__device__ __nv_bfloat16 g_wkl[(size_t)NKV * IDIM];
__device__ __nv_bfloat16 g_wvh[(size_t)NKV * IDIM];
__device__ __nv_bfloat16 g_wvl[(size_t)NKV * IDIM];
__device__ __nv_bfloat16 g_woh[(size_t)IDIM * ODIM];
__device__ __nv_bfloat16 g_wol[(size_t)IDIM * ODIM];
__device__ __nv_bfloat16 g_ath[(size_t)L_SEQ * ODIM];
__device__ __nv_bfloat16 g_atl[(size_t)L_SEQ * ODIM];

// ---------------- split kernel: fp32 -> (hi, lo) bf16 ----------------
__global__ __launch_bounds__(256) void split_kernel(
    const float* __restrict__ in, __nv_bfloat16* __restrict__ hi,
    __nv_bfloat16* __restrict__ lo, size_t n4)
{
    size_t i = (size_t)blockIdx.x * blockDim.x + threadIdx.x;
    size_t stride = (size_t)gridDim.x * blockDim.x;
    for (; i < n4; i += stride) {
        float4 v = reinterpret_cast<const float4*>(in)[i];
        __nv_bfloat16 h0 = __float2bfloat16(v.x), h1 = __float2bfloat16(v.y);
        __nv_bfloat16 h2 = __float2bfloat16(v.z), h3 = __float2bfloat16(v.w);
        __nv_bfloat16 l0 = __float2bfloat16(v.x - __bfloat162float(h0));
        __nv_bfloat16 l1 = __float2bfloat16(v.y - __bfloat162float(h1));
        __nv_bfloat16 l2 = __float2bfloat16(v.z - __bfloat162float(h2));
        __nv_bfloat16 l3 = __float2bfloat16(v.w - __bfloat162float(h3));
        __nv_bfloat162 hp0{h0, h1}, hp1{h2, h3}, lp0{l0, l1}, lp1{l2, l3};
        reinterpret_cast<__nv_bfloat162*>(hi)[i*2]   = hp0;
        reinterpret_cast<__nv_bfloat162*>(hi)[i*2+1] = hp1;
        reinterpret_cast<__nv_bfloat162*>(lo)[i*2]   = lp0;
        reinterpret_cast<__nv_bfloat162*>(lo)[i*2+1] = lp1;
    }
}

// ---------------- transpose + split: W[K][N] fp32 -> Wt hi/lo [N][K] bf16 ----------------
__global__ __launch_bounds__(256) void transpose_split_kernel(
    const float* __restrict__ W, __nv_bfloat16* __restrict__ Th,
    __nv_bfloat16* __restrict__ Tl, int Kdim, int Ndim)
{
    __shared__ float tile[32][33];
    int n0 = blockIdx.x * 32;
    int k0 = blockIdx.y * 32;
    int tx = threadIdx.x & 31;
    int ty = threadIdx.x >> 5;      // 0..7
#pragma unroll
    for (int r = 0; r < 4; r++)
        tile[ty + 8*r][tx] = W[(size_t)(k0 + ty + 8*r) * Ndim + n0 + tx];
    __syncthreads();
#pragma unroll
    for (int r = 0; r < 4; r++) {
        float v = tile[tx][ty + 8*r];
        __nv_bfloat16 h = __float2bfloat16(v);
        __nv_bfloat16 l = __float2bfloat16(v - __bfloat162float(h));
        size_t o = (size_t)(n0 + ty + 8*r) * Kdim + k0 + tx;
        Th[o] = h; Tl[o] = l;
    }
}

// ---------------- warp-mma split-bf16 GEMM ----------------
// C[M x N] fp32 = A[M x 2048] @ Bt[N x 2048]^T  via  Ah·Bh + Ah·Bl + Al·Bh
// block 128x128, BK=32, 8 warps (2 M-groups x 4 N-groups), warp tile 64x32.
#define GBK 32
#define NCHUNK (IDIM / GBK)            // 64
#define RS 80                          // smem row stride bytes (40 bf16, conflict-free ldsm)
#define MAT_BYTES (128 * RS)           // 10240
#define STAGE_BYTES (4 * MAT_BYTES)    // 40960 (Ah, Al, Bh, Bl)

__global__ __launch_bounds__(256) void mma_gemm(
    const __nv_bfloat16* __restrict__ Ah, const __nv_bfloat16* __restrict__ Al,
    const __nv_bfloat16* __restrict__ Bh, const __nv_bfloat16* __restrict__ Bl,
    float* __restrict__ C, int N)
{
    extern __shared__ char smem[];
    const uint32_t sb = smem_to_u32(smem);

    const int tid  = threadIdx.x;
    const int lane = tid & 31;
    const int wid  = tid >> 5;
    const int wm   = wid & 1;          // 0..1
    const int wn   = wid >> 1;         // 0..3
    const int m0   = blockIdx.y * 128;
    const int n0   = blockIdx.x * 128;

    // ---- async load assignment: matrix = tid>>6 (0=Ah,1=Al,2=Bh,3=Bl) ----
    const int mat  = tid >> 6;
    const int lidx = tid & 63;
    const __nv_bfloat16* gbase = (mat == 0) ? Ah : (mat == 1) ? Al : (mat == 2) ? Bh : Bl;
    const int grow0 = (mat < 2) ? m0 : n0;
    const uint32_t smat = sb + mat * MAT_BYTES;

    auto issue_loads = [&](int chunk) {
        const int stage = chunk & 1;
        const uint32_t sdst0 = smat + stage * STAGE_BYTES;
        const __nv_bfloat16* src0 = gbase + (size_t)grow0 * IDIM + chunk * GBK;
#pragma unroll
        for (int j = 0; j < 8; j++) {
            int idx = lidx + 64 * j;       // 0..511
            int row = idx >> 2;            // 0..127
            int c   = idx & 3;             // 16B column
            cp_async16(sdst0 + row * RS + c * 16,
                       src0 + (size_t)row * IDIM + c * 8);
        }
    };

    float acc[4][4][4];
#pragma unroll
    for (int mi = 0; mi < 4; mi++)
#pragma unroll
        for (int ni = 0; ni < 4; ni++)
#pragma unroll
            for (int r = 0; r < 4; r++) acc[mi][ni][r] = 0.0f;

    // per-thread ldmatrix base offsets
    const uint32_t a_row = wm * 64 + (lane & 15);
    const uint32_t b_row = wn * 32 + (lane & 15);
    const uint32_t colb  = (lane >> 4) * 16;   // 0 or 16 bytes (k +8 elems)

    issue_loads(0); CP_COMMIT();

    for (int i = 0; i < NCHUNK; i++) {
        const int stage = i & 1;
        if (i + 1 < NCHUNK) { issue_loads(i + 1); CP_COMMIT(); CP_WAIT1(); }
        else                { CP_WAIT0(); }
        __syncthreads();

        const uint32_t sAh = sb + stage * STAGE_BYTES;
        const uint32_t sAl = sAh + MAT_BYTES;
        const uint32_t sBh = sAh + 2 * MAT_BYTES;
        const uint32_t sBl = sAh + 3 * MAT_BYTES;

#pragma unroll
        for (int ks = 0; ks < 2; ks++) {
            const uint32_t kb = ks * 32 + colb;   // byte offset along k
            uint32_t ah[4][4], al[4][4], bh[2][4], bl[2][4];
#pragma unroll
            for (int mi = 0; mi < 4; mi++) {
                uint32_t ro = (a_row + mi * 16) * RS + kb;
                ldsm_x4(ah[mi], sAh + ro);
                ldsm_x4(al[mi], sAl + ro);
            }
#pragma unroll
            for (int nt = 0; nt < 2; nt++) {
                uint32_t ro = (b_row + nt * 16) * RS + kb;
                ldsm_x4(bh[nt], sBh + ro);
                ldsm_x4(bl[nt], sBl + ro);
            }
#pragma unroll
            for (int mi = 0; mi < 4; mi++) {
#pragma unroll
                for (int ni = 0; ni < 4; ni++) {
                    const int nt = ni >> 1, sub = ni & 1;
                    mma16816(acc[mi][ni], ah[mi], bh[nt][sub], bh[nt][2 + sub]);
                    mma16816(acc[mi][ni], ah[mi], bl[nt][sub], bl[nt][2 + sub]);
                    mma16816(acc[mi][ni], al[mi], bh[nt][sub], bh[nt][2 + sub]);
                }
            }
        }
        __syncthreads();
    }

    // ---- epilogue: fragment layout -> global fp32 ----
    const int er = lane >> 2;          // 0..7
    const int ec = (lane & 3) * 2;     // 0,2,4,6
#pragma unroll
    for (int mi = 0; mi < 4; mi++) {
#pragma unroll
        for (int ni = 0; ni < 4; ni++) {
            int row = m0 + wm * 64 + mi * 16 + er;
            int col = n0 + wn * 32 + ni * 8 + ec;
            *reinterpret_cast<float2*>(&C[(size_t)row * N + col]) =
                make_float2(acc[mi][ni][0], acc[mi][ni][1]);
            *reinterpret_cast<float2*>(&C[(size_t)(row + 8) * N + col]) =
                make_float2(acc[mi][ni][2], acc[mi][ni][3]);
        }
    }
}

// ---------------- RMSNorm + partial RoPE for Q (+ gate extraction) ----------------
__global__ __launch_bounds__(256) void qnorm_rope_kernel(
    const float* __restrict__ cosb, const float* __restrict__ sinb,
    const float* __restrict__ gamma)
{
    const int l = blockIdx.x;
    const int h = blockIdx.y;
    const int d = threadIdx.x;
    const float* row = g_qraw + (size_t)l * (ODIM * 2) + h * 512;
    float v  = row[d];
    float gv = row[256 + d];

    float s = v * v;
#pragma unroll
    for (int o = 16; o > 0; o >>= 1) s += __shfl_xor_sync(0xffffffffu, s, o);
    __shared__ float wsum[8];
    __shared__ float sh[256];
    if ((d & 31) == 0) wsum[d >> 5] = s;
    __syncthreads();
    float tot = 0.0f;
#pragma unroll
    for (int w = 0; w < 8; w++) tot += wsum[w];
    float rstd = rsqrtf(tot * (1.0f / 256.0f) + 1e-6f);
    float y = v * rstd * gamma[d];
    sh[d] = y;
    __syncthreads();
    float out = y;
    if (d < ROPED) {
        float rot = (d < ROPED / 2) ? -sh[d + ROPED / 2] : sh[d - ROPED / 2];
        out = y * cosb[(size_t)l * ROPED + d] + rot * sinb[(size_t)l * ROPED + d];
    }
    g_q   [(size_t)l * ODIM + h * HDIM + d] = out;
    g_gate[(size_t)l * ODIM + h * HDIM + d] = gv;
}

// ---------------- RMSNorm + partial RoPE for K ----------------
__global__ __launch_bounds__(256) void knorm_rope_kernel(
    const float* __restrict__ cosb, const float* __restrict__ sinb,
    const float* __restrict__ gamma)
{
    const int l = blockIdx.x;
    const int g = blockIdx.y;
    const int d = threadIdx.x;
    float v = g_kraw[(size_t)l * NKV + g * HDIM + d];

    float s = v * v;
#pragma unroll
    for (int o = 16; o > 0; o >>= 1) s += __shfl_xor_sync(0xffffffffu, s, o);
    __shared__ float wsum[8];
    __shared__ float sh[256];
    if ((d & 31) == 0) wsum[d >> 5] = s;
    __syncthreads();
    float tot = 0.0f;
#pragma unroll
    for (int w = 0; w < 8; w++) tot += wsum[w];
    float rstd = rsqrtf(tot * (1.0f / 256.0f) + 1e-6f);
    float y = v * rstd * gamma[d];
    sh[d] = y;
    __syncthreads();
    float out = y;
    if (d < ROPED) {
        float rot = (d < ROPED / 2) ? -sh[d + ROPED / 2] : sh[d - ROPED / 2];
        out = y * cosb[(size_t)l * ROPED + d] + rot * sinb[(size_t)l * ROPED + d];
    }
    g_k[(size_t)l * NKV + g * HDIM + d] = out;
}

// ---------------- Flash attention, fp32, Br=Bc=64, D=256 ----------------
#define BR 64
#define BC 64
#define SS_STRIDE 68

__global__ __launch_bounds__(256, 1) void attn_kernel()
{
    extern __shared__ float fsm[];
    float* Qst  = fsm;
    float* Kst  = Qst + 256 * 64;
    float* Vs   = Kst + 256 * 64;
    float* Ss   = Vs  + 64 * 256;
    float* mrow = Ss  + 64 * SS_STRIDE;
    float* lrow = mrow + 64;
    float* crow = lrow + 64;

    const int tid = threadIdx.x;
    const int qt  = gridDim.x - 1 - blockIdx.x;
    const int h   = blockIdx.y;
    const int g   = h >> 2;
    const int i0  = qt * BR;

    {
        const int j   = tid >> 2;
        const int c4b = tid & 3;
#pragma unroll
        for (int p = 0; p < 16; p++) {
            int c4 = c4b + 4 * p;
            float4 a = *reinterpret_cast<const float4*>(
                &g_q[((size_t)(i0 + j) * NHEADS + h) * HDIM + c4 * 4]);
            Qst[(c4 * 4 + 0) * 64 + j] = a.x * QSCALE;
            Qst[(c4 * 4 + 1) * 64 + j] = a.y * QSCALE;
            Qst[(c4 * 4 + 2) * 64 + j] = a.z * QSCALE;
            Qst[(c4 * 4 + 3) * 64 + j] = a.w * QSCALE;
        }
    }
    if (tid < 64) { mrow[tid] = -INFINITY; lrow[tid] = 0.0f; }

    const int oty = tid >> 5;
    const int otx = tid & 31;
    float oacc[8][8];
#pragma unroll
    for (int i = 0; i < 8; i++)
#pragma unroll
        for (int jj = 0; jj < 8; jj++) oacc[i][jj] = 0.0f;

    const int sty = tid >> 4;
    const int stx = tid & 15;

    for (int j0 = 0; j0 <= i0; j0 += BC) {
        __syncthreads();

        {
            const int j   = tid >> 2;
            const int c4b = tid & 3;
#pragma unroll
            for (int p = 0; p < 16; p++) {
                int c4 = c4b + 4 * p;
                float4 a = *reinterpret_cast<const float4*>(
                    &g_k[((size_t)(j0 + j) * NGROUPS + g) * HDIM + c4 * 4]);
                Kst[(c4 * 4 + 0) * 64 + j] = a.x;
                Kst[(c4 * 4 + 1) * 64 + j] = a.y;
                Kst[(c4 * 4 + 2) * 64 + j] = a.z;
                Kst[(c4 * 4 + 3) * 64 + j] = a.w;
            }
        }
        {
#pragma unroll
            for (int p = 0; p < 16; p++) {
                int f  = tid + 256 * p;
                int r  = f >> 6;
                int c4 = f & 63;
                *reinterpret_cast<float4*>(&Vs[r * 256 + c4 * 4]) =
                    *reinterpret_cast<const float4*>(
                        &g_v[((size_t)(j0 + r) * NGROUPS + g) * HDIM + c4 * 4]);
            }
        }
        __syncthreads();

        float sacc[4][4];
#pragma unroll
        for (int i = 0; i < 4; i++)
#pragma unroll
            for (int j = 0; j < 4; j++) sacc[i][j] = 0.0f;

        const float* qp = &Qst[sty * 4];
        const float* kp = &Kst[stx * 4];
#pragma unroll 8
        for (int k = 0; k < 256; k++) {
            float4 qa = *reinterpret_cast<const float4*>(qp + k * 64);
            float4 kb = *reinterpret_cast<const float4*>(kp + k * 64);
            float qv[4] = {qa.x, qa.y, qa.z, qa.w};
            float kv[4] = {kb.x, kb.y, kb.z, kb.w};
#pragma unroll
            for (int i = 0; i < 4; i++)
#pragma unroll
                for (int j = 0; j < 4; j++) sacc[i][j] += qv[i] * kv[j];
        }
#pragma unroll
        for (int i = 0; i < 4; i++) {
            int r = sty * 4 + i;
#pragma unroll
            for (int j = 0; j < 4; j++) {
                int c = stx * 4 + j;
                float sv = sacc[i][j];
                if (j0 + c > i0 + r) sv = -INFINITY;
                Ss[r * SS_STRIDE + c] = sv;
            }
        }
        __syncthreads();

        if (tid < 64) {
            const int r = tid;
            float mold = mrow[r];
            float mnew = mold;
#pragma unroll 8
            for (int c = 0; c < 64; c++) mnew = fmaxf(mnew, Ss[r * SS_STRIDE + c]);
            float corr = __expf(mold - mnew);
            float lsum = lrow[r] * corr;
#pragma unroll 8
            for (int c = 0; c < 64; c++) {
                float pv = __expf(Ss[r * SS_STRIDE + c] - mnew);
                Ss[r * SS_STRIDE + c] = pv;
                lsum += pv;
            }
            mrow[r] = mnew; lrow[r] = lsum; crow[r] = corr;
        }
        __syncthreads();

#pragma unroll
        for (int i = 0; i < 8; i++) {
            float c = crow[oty * 8 + i];
#pragma unroll
            for (int jj = 0; jj < 8; jj++) oacc[i][jj] *= c;
        }
#pragma unroll 2
        for (int j = 0; j < 64; j++) {
            float4 v0 = *reinterpret_cast<const float4*>(&Vs[j * 256 + otx * 8]);
            float4 v1 = *reinterpret_cast<const float4*>(&Vs[j * 256 + otx * 8 + 4]);
#pragma unroll
            for (int i = 0; i < 8; i++) {
                float pv = Ss[(oty * 8 + i) * SS_STRIDE + j];
                oacc[i][0] += pv * v0.x; oacc[i][1] += pv * v0.y;
                oacc[i][2] += pv * v0.z; oacc[i][3] += pv * v0.w;
                oacc[i][4] += pv * v1.x; oacc[i][5] += pv * v1.y;
                oacc[i][6] += pv * v1.z; oacc[i][7] += pv * v1.w;
            }
        }
    }

#pragma unroll
    for (int i = 0; i < 8; i++) {
        int r = oty * 8 + i;
        float linv = 1.0f / lrow[r];
        size_t base = (size_t)(i0 + r) * ODIM + h * HDIM + otx * 8;
        float4 g0 = *reinterpret_cast<const float4*>(&g_gate[base]);
        float4 g1 = *reinterpret_cast<const float4*>(&g_gate[base + 4]);
        float gv[8] = {g0.x, g0.y, g0.z, g0.w, g1.x, g1.y, g1.z, g1.w};
        float res[8];
#pragma unroll
        for (int jj = 0; jj < 8; jj++) {
            float sig = 1.0f / (1.0f + __expf(-gv[jj]));
            res[jj] = oacc[i][jj] * linv * sig;
        }
        *reinterpret_cast<float4*>(&g_att[base])     = make_float4(res[0], res[1], res[2], res[3]);
        *reinterpret_cast<float4*>(&g_att[base + 4]) = make_float4(res[4], res[5], res[6], res[7]);
    }
}

// ---------------- launch ----------------
extern "C" void kernel_launch(void* const* d_in, const int* in_sizes, int n_in,
                              void* d_out, int out_size)
{
    const float* x    = (const float*)d_in[0];
    const float* cosb = (const float*)d_in[1];
    const float* sinb = (const float*)d_in[2];
    const float* wq   = (const float*)d_in[4];
    const float* wk   = (const float*)d_in[5];
    const float* wv   = (const float*)d_in[6];
    const float* wo   = (const float*)d_in[7];
    const float* qg   = (const float*)d_in[8];
    const float* kg   = (const float*)d_in[9];
    float* out        = (float*)d_out;

    float *p_qraw, *p_kraw, *p_v, *p_att;
    cudaGetSymbolAddress((void**)&p_qraw, g_qraw);
    cudaGetSymbolAddress((void**)&p_kraw, g_kraw);
    cudaGetSymbolAddress((void**)&p_v,    g_v);
    cudaGetSymbolAddress((void**)&p_att,  g_att);

    __nv_bfloat16 *p_xh, *p_xl, *p_wqh, *p_wql, *p_wkh, *p_wkl, *p_wvh, *p_wvl,
                  *p_woh, *p_wol, *p_ath, *p_atl;
    cudaGetSymbolAddress((void**)&p_xh,  g_xh);
    cudaGetSymbolAddress((void**)&p_xl,  g_xl);
    cudaGetSymbolAddress((void**)&p_wqh, g_wqh);
    cudaGetSymbolAddress((void**)&p_wql, g_wql);
    cudaGetSymbolAddress((void**)&p_wkh, g_wkh);
    cudaGetSymbolAddress((void**)&p_wkl, g_wkl);
    cudaGetSymbolAddress((void**)&p_wvh, g_wvh);
    cudaGetSymbolAddress((void**)&p_wvl, g_wvl);
    cudaGetSymbolAddress((void**)&p_woh, g_woh);
    cudaGetSymbolAddress((void**)&p_wol, g_wol);
    cudaGetSymbolAddress((void**)&p_ath, g_ath);
    cudaGetSymbolAddress((void**)&p_atl, g_atl);

    const int gemm_smem = 2 * STAGE_BYTES;   // 81920
    cudaFuncSetAttribute(mma_gemm, cudaFuncAttributeMaxDynamicSharedMemorySize, gemm_smem);

    // 0) operand prep: split x; transpose+split weights
    split_kernel<<<1024, 256>>>(x, p_xh, p_xl, (size_t)L_SEQ * IDIM / 4);
    transpose_split_kernel<<<dim3((ODIM*2)/32, IDIM/32), 256>>>(wq, p_wqh, p_wql, IDIM, ODIM*2);
    transpose_split_kernel<<<dim3(NKV/32,      IDIM/32), 256>>>(wk, p_wkh, p_wkl, IDIM, NKV);
    transpose_split_kernel<<<dim3(NKV/32,      IDIM/32), 256>>>(wv, p_wvh, p_wvl, IDIM, NKV);
    transpose_split_kernel<<<dim3(IDIM/32,     ODIM/32), 256>>>(wo, p_woh, p_wol, ODIM, IDIM);

    // 1) projections (warp-mma split-bf16)
    mma_gemm<<<dim3((ODIM*2)/128, L_SEQ/128), 256, gemm_smem>>>(p_xh, p_xl, p_wqh, p_wql, p_qraw, ODIM*2);
    mma_gemm<<<dim3(NKV/128,      L_SEQ/128), 256, gemm_smem>>>(p_xh, p_xl, p_wkh, p_wkl, p_kraw, NKV);
    mma_gemm<<<dim3(NKV/128,      L_SEQ/128), 256, gemm_smem>>>(p_xh, p_xl, p_wvh, p_wvl, p_v,    NKV);

    // 2) RMSNorm + RoPE (+ gate split)
    qnorm_rope_kernel<<<dim3(L_SEQ, NHEADS),  256>>>(cosb, sinb, qg);
    knorm_rope_kernel<<<dim3(L_SEQ, NGROUPS), 256>>>(cosb, sinb, kg);

    // 3) causal flash attention + gating (fp32)
    const int attn_smem = (256 * 64 * 2 + 64 * 256 + 64 * SS_STRIDE + 3 * 64) * sizeof(float);
    cudaFuncSetAttribute(attn_kernel, cudaFuncAttributeMaxDynamicSharedMemorySize, attn_smem);
    attn_kernel<<<dim3(L_SEQ / BR, NHEADS), 256, attn_smem>>>();

    // 4) output projection (warp-mma split-bf16)
    split_kernel<<<1024, 256>>>(p_att, p_ath, p_atl, (size_t)L_SEQ * ODIM / 4);
    mma_gemm<<<dim3(IDIM/128, L_SEQ/128), 256, gemm_smem>>>(p_ath, p_atl, p_woh, p_wol, out, IDIM);
}

// round 4
// speedup vs baseline: 2.4639x; 1.7750x over previous
#include <cuda_runtime.h>
#include <cuda_bf16.h>
#include <math.h>
#include <stdint.h>

// ---------------- problem constants ----------------
#define L_SEQ   4096
#define IDIM    2048
#define NHEADS  8
#define NGROUPS 2
#define HDIM    256
#define ROPED   64
#define ODIM    (NHEADS*HDIM)     // 2048
#define NKV     (NGROUPS*HDIM)    // 512
#define QSCALE  0.0625f           // 256^-0.5

// ---------------- warp-MMA helpers (standard PTX, sm_80+) ----------------
__device__ __forceinline__ void ldsm_x4(uint32_t* r, uint32_t addr) {
    asm volatile("ldmatrix.sync.aligned.m8n8.x4.shared.b16 {%0,%1,%2,%3}, [%4];"
        : "=r"(r[0]), "=r"(r[1]), "=r"(r[2]), "=r"(r[3]) : "r"(addr));
}
__device__ __forceinline__ void ldsm_x4_trans(uint32_t* r, uint32_t addr) {
    asm volatile("ldmatrix.sync.aligned.m8n8.x4.trans.shared.b16 {%0,%1,%2,%3}, [%4];"
        : "=r"(r[0]), "=r"(r[1]), "=r"(r[2]), "=r"(r[3]) : "r"(addr));
}
__device__ __forceinline__ void mma16816(float* d, const uint32_t* a, uint32_t b0, uint32_t b1) {
    asm volatile("mma.sync.aligned.m16n8k16.row.col.f32.bf16.bf16.f32 "
        "{%0,%1,%2,%3}, {%4,%5,%6,%7}, {%8,%9}, {%0,%1,%2,%3};"
        : "+f"(d[0]), "+f"(d[1]), "+f"(d[2]), "+f"(d[3])
        : "r"(a[0]), "r"(a[1]), "r"(a[2]), "r"(a[3]), "r"(b0), "r"(b1));
}
__device__ __forceinline__ void cp_async16(uint32_t dst, const void* src) {
    asm volatile("cp.async.cg.shared.global [%0], [%1], 16;" :: "r"(dst), "l"(src));
}
#define CP_COMMIT() asm volatile("cp.async.commit_group;" ::: "memory")
#define CP_WAIT1()  asm volatile("cp.async.wait_group 1;" ::: "memory")
#define CP_WAIT0()  asm volatile("cp.async.wait_group 0;" ::: "memory")

__device__ __forceinline__ uint32_t smem_to_u32(const void* p) {
    uint32_t a;
    asm("{ .reg .u64 t; cvta.to.shared.u64 t, %1; cvt.u32.u64 %0, t; }" : "=r"(a) : "l"(p));
    return a;
}
__device__ __forceinline__ uint32_t pack_bf16x2(__nv_bfloat16 a, __nv_bfloat16 b) {
    __nv_bfloat162 t{a, b};
    return *reinterpret_cast<uint32_t*>(&t);
}

// ---------------- scratch (device globals) ----------------
__device__ float g_qraw[(size_t)L_SEQ * (ODIM*2)];
__device__ float g_gate[(size_t)L_SEQ * ODIM];
__device__ float g_kraw[(size_t)L_SEQ * NKV];
__device__ float g_v   [(size_t)L_SEQ * NKV];

// bf16 hi/lo operands
__device__ __nv_bfloat16 g_xh [(size_t)L_SEQ * IDIM];
__device__ __nv_bfloat16 g_xl [(size_t)L_SEQ * IDIM];
__device__ __nv_bfloat16 g_wqh[(size_t)(ODIM*2) * IDIM];
__device__ __nv_bfloat16 g_wql[(size_t)(ODIM*2) * IDIM];
__device__ __nv_bfloat16 g_wkh[(size_t)NKV * IDIM];
__device__ __nv_bfloat16 g_wkl[(size_t)NKV * IDIM];
__device__ __nv_bfloat16 g_wvh[(size_t)NKV * IDIM];
__device__ __nv_bfloat16 g_wvl[(size_t)NKV * IDIM];
__device__ __nv_bfloat16 g_woh[(size_t)IDIM * ODIM];
__device__ __nv_bfloat16 g_wol[(size_t)IDIM * ODIM];
__device__ __nv_bfloat16 g_ath[(size_t)L_SEQ * ODIM];
__device__ __nv_bfloat16 g_atl[(size_t)L_SEQ * ODIM];
// attention operands
__device__ __nv_bfloat16 g_qh [(size_t)L_SEQ * ODIM];
__device__ __nv_bfloat16 g_ql [(size_t)L_SEQ * ODIM];
__device__ __nv_bfloat16 g_kh [(size_t)L_SEQ * NKV];
__device__ __nv_bfloat16 g_kl [(size_t)L_SEQ * NKV];
__device__ __nv_bfloat16 g_vh [(size_t)L_SEQ * NKV];
__device__ __nv_bfloat16 g_vl [(size_t)L_SEQ * NKV];

// ---------------- split kernel: fp32 -> (hi, lo) bf16 ----------------
__global__ __launch_bounds__(256) void split_kernel(
    const float* __restrict__ in, __nv_bfloat16* __restrict__ hi,
    __nv_bfloat16* __restrict__ lo, size_t n4)
{
    size_t i = (size_t)blockIdx.x * blockDim.x + threadIdx.x;
    size_t stride = (size_t)gridDim.x * blockDim.x;
    for (; i < n4; i += stride) {
        float4 v = reinterpret_cast<const float4*>(in)[i];
        __nv_bfloat16 h0 = __float2bfloat16(v.x), h1 = __float2bfloat16(v.y);
        __nv_bfloat16 h2 = __float2bfloat16(v.z), h3 = __float2bfloat16(v.w);
        __nv_bfloat16 l0 = __float2bfloat16(v.x - __bfloat162float(h0));
        __nv_bfloat16 l1 = __float2bfloat16(v.y - __bfloat162float(h1));
        __nv_bfloat16 l2 = __float2bfloat16(v.z - __bfloat162float(h2));
        __nv_bfloat16 l3 = __float2bfloat16(v.w - __bfloat162float(h3));
        __nv_bfloat162 hp0{h0, h1}, hp1{h2, h3}, lp0{l0, l1}, lp1{l2, l3};
        reinterpret_cast<__nv_bfloat162*>(hi)[i*2]   = hp0;
        reinterpret_cast<__nv_bfloat162*>(hi)[i*2+1] = hp1;
        reinterpret_cast<__nv_bfloat162*>(lo)[i*2]   = lp0;
        reinterpret_cast<__nv_bfloat162*>(lo)[i*2+1] = lp1;
    }
}

// ---------------- transpose + split: W[K][N] fp32 -> Wt hi/lo [N][K] bf16 ----------------
__global__ __launch_bounds__(256) void transpose_split_kernel(
    const float* __restrict__ W, __nv_bfloat16* __restrict__ Th,
    __nv_bfloat16* __restrict__ Tl, int Kdim, int Ndim)
{
    __shared__ float tile[32][33];
    int n0 = blockIdx.x * 32;
    int k0 = blockIdx.y * 32;
    int tx = threadIdx.x & 31;
    int ty = threadIdx.x >> 5;
#pragma unroll
    for (int r = 0; r < 4; r++)
        tile[ty + 8*r][tx] = W[(size_t)(k0 + ty + 8*r) * Ndim + n0 + tx];
    __syncthreads();
#pragma unroll
    for (int r = 0; r < 4; r++) {
        float v = tile[tx][ty + 8*r];
        __nv_bfloat16 h = __float2bfloat16(v);
        __nv_bfloat16 l = __float2bfloat16(v - __bfloat162float(h));
        size_t o = (size_t)(n0 + ty + 8*r) * Kdim + k0 + tx;
        Th[o] = h; Tl[o] = l;
    }
}

// ---------------- warp-mma split-bf16 GEMM (unchanged, proven) ----------------
#define GBK 32
#define NCHUNK (IDIM / GBK)
#define RS 80
#define MAT_BYTES (128 * RS)
#define STAGE_BYTES (4 * MAT_BYTES)

__global__ __launch_bounds__(256) void mma_gemm(
    const __nv_bfloat16* __restrict__ Ah, const __nv_bfloat16* __restrict__ Al,
    const __nv_bfloat16* __restrict__ Bh, const __nv_bfloat16* __restrict__ Bl,
    float* __restrict__ C, int N)
{
    extern __shared__ char smem[];
    const uint32_t sb = smem_to_u32(smem);

    const int tid  = threadIdx.x;
    const int lane = tid & 31;
    const int wid  = tid >> 5;
    const int wm   = wid & 1;
    const int wn   = wid >> 1;
    const int m0   = blockIdx.y * 128;
    const int n0   = blockIdx.x * 128;

    const int mat  = tid >> 6;
    const int lidx = tid & 63;
    const __nv_bfloat16* gbase = (mat == 0) ? Ah : (mat == 1) ? Al : (mat == 2) ? Bh : Bl;
    const int grow0 = (mat < 2) ? m0 : n0;
    const uint32_t smat = sb + mat * MAT_BYTES;

    auto issue_loads = [&](int chunk) {
        const int stage = chunk & 1;
        const uint32_t sdst0 = smat + stage * STAGE_BYTES;
        const __nv_bfloat16* src0 = gbase + (size_t)grow0 * IDIM + chunk * GBK;
#pragma unroll
        for (int j = 0; j < 8; j++) {
            int idx = lidx + 64 * j;
            int row = idx >> 2;
            int c   = idx & 3;
            cp_async16(sdst0 + row * RS + c * 16,
                       src0 + (size_t)row * IDIM + c * 8);
        }
    };

    float acc[4][4][4];
#pragma unroll
    for (int mi = 0; mi < 4; mi++)
#pragma unroll
        for (int ni = 0; ni < 4; ni++)
#pragma unroll
            for (int r = 0; r < 4; r++) acc[mi][ni][r] = 0.0f;

    const uint32_t a_row = wm * 64 + (lane & 15);
    const uint32_t b_row = wn * 32 + (lane & 15);
    const uint32_t colb  = (lane >> 4) * 16;

    issue_loads(0); CP_COMMIT();

    for (int i = 0; i < NCHUNK; i++) {
        const int stage = i & 1;
        if (i + 1 < NCHUNK) { issue_loads(i + 1); CP_COMMIT(); CP_WAIT1(); }
        else                { CP_WAIT0(); }
        __syncthreads();

        const uint32_t sAh = sb + stage * STAGE_BYTES;
        const uint32_t sAl = sAh + MAT_BYTES;
        const uint32_t sBh = sAh + 2 * MAT_BYTES;
        const uint32_t sBl = sAh + 3 * MAT_BYTES;

#pragma unroll
        for (int ks = 0; ks < 2; ks++) {
            const uint32_t kb = ks * 32 + colb;
            uint32_t ah[4][4], al[4][4], bh[2][4], bl[2][4];
#pragma unroll
            for (int mi = 0; mi < 4; mi++) {
                uint32_t ro = (a_row + mi * 16) * RS + kb;
                ldsm_x4(ah[mi], sAh + ro);
                ldsm_x4(al[mi], sAl + ro);
            }
#pragma unroll
            for (int nt = 0; nt < 2; nt++) {
                uint32_t ro = (b_row + nt * 16) * RS + kb;
                ldsm_x4(bh[nt], sBh + ro);
                ldsm_x4(bl[nt], sBl + ro);
            }
#pragma unroll
            for (int mi = 0; mi < 4; mi++) {
#pragma unroll
                for (int ni = 0; ni < 4; ni++) {
                    const int nt = ni >> 1, sub = ni & 1;
                    mma16816(acc[mi][ni], ah[mi], bh[nt][sub], bh[nt][2 + sub]);
                    mma16816(acc[mi][ni], ah[mi], bl[nt][sub], bl[nt][2 + sub]);
                    mma16816(acc[mi][ni], al[mi], bh[nt][sub], bh[nt][2 + sub]);
                }
            }
        }
        __syncthreads();
    }

    const int er = lane >> 2;
    const int ec = (lane & 3) * 2;
#pragma unroll
    for (int mi = 0; mi < 4; mi++) {
#pragma unroll
        for (int ni = 0; ni < 4; ni++) {
            int row = m0 + wm * 64 + mi * 16 + er;
            int col = n0 + wn * 32 + ni * 8 + ec;
            *reinterpret_cast<float2*>(&C[(size_t)row * N + col]) =
                make_float2(acc[mi][ni][0], acc[mi][ni][1]);
            *reinterpret_cast<float2*>(&C[(size_t)(row + 8) * N + col]) =
                make_float2(acc[mi][ni][2], acc[mi][ni][3]);
        }
    }
}

// ---------------- RMSNorm + RoPE for Q -> bf16 hi/lo (pre-scaled) + gate ----------------
__global__ __launch_bounds__(256) void qnorm_rope_kernel(
    const float* __restrict__ cosb, const float* __restrict__ sinb,
    const float* __restrict__ gamma)
{
    const int l = blockIdx.x;
    const int h = blockIdx.y;
    const int d = threadIdx.x;
    const float* row = g_qraw + (size_t)l * (ODIM * 2) + h * 512;
    float v  = row[d];
    float gv = row[256 + d];

    float s = v * v;
#pragma unroll
    for (int o = 16; o > 0; o >>= 1) s += __shfl_xor_sync(0xffffffffu, s, o);
    __shared__ float wsum[8];
    __shared__ float sh[256];
    if ((d & 31) == 0) wsum[d >> 5] = s;
    __syncthreads();
    float tot = 0.0f;
#pragma unroll
    for (int w = 0; w < 8; w++) tot += wsum[w];
    float rstd = rsqrtf(tot * (1.0f / 256.0f) + 1e-6f);
    float y = v * rstd * gamma[d];
    sh[d] = y;
    __syncthreads();
    float out = y;
    if (d < ROPED) {
        float rot = (d < ROPED / 2) ? -sh[d + ROPED / 2] : sh[d - ROPED / 2];
        out = y * cosb[(size_t)l * ROPED + d] + rot * sinb[(size_t)l * ROPED + d];
    }
    float q = out * QSCALE;
    __nv_bfloat16 qh = __float2bfloat16(q);
    __nv_bfloat16 ql = __float2bfloat16(q - __bfloat162float(qh));
    size_t o = (size_t)l * ODIM + h * HDIM + d;
    g_qh[o] = qh; g_ql[o] = ql;
    g_gate[o] = gv;
}

// ---------------- RMSNorm + RoPE for K -> bf16 hi/lo ----------------
__global__ __launch_bounds__(256) void knorm_rope_kernel(
    const float* __restrict__ cosb, const float* __restrict__ sinb,
    const float* __restrict__ gamma)
{
    const int l = blockIdx.x;
    const int g = blockIdx.y;
    const int d = threadIdx.x;
    float v = g_kraw[(size_t)l * NKV + g * HDIM + d];

    float s = v * v;
#pragma unroll
    for (int o = 16; o > 0; o >>= 1) s += __shfl_xor_sync(0xffffffffu, s, o);
    __shared__ float wsum[8];
    __shared__ float sh[256];
    if ((d & 31) == 0) wsum[d >> 5] = s;
    __syncthreads();
    float tot = 0.0f;
#pragma unroll
    for (int w = 0; w < 8; w++) tot += wsum[w];
    float rstd = rsqrtf(tot * (1.0f / 256.0f) + 1e-6f);
    float y = v * rstd * gamma[d];
    sh[d] = y;
    __syncthreads();
    float out = y;
    if (d < ROPED) {
        float rot = (d < ROPED / 2) ? -sh[d + ROPED / 2] : sh[d - ROPED / 2];
        out = y * cosb[(size_t)l * ROPED + d] + rot * sinb[(size_t)l * ROPED + d];
    }
    __nv_bfloat16 kh = __float2bfloat16(out);
    __nv_bfloat16 kl = __float2bfloat16(out - __bfloat162float(kh));
    size_t o = (size_t)l * NKV + g * HDIM + d;
    g_kh[o] = kh; g_kl[o] = kl;
}

// ---------------- MMA flash attention (split-bf16), BR=BC=64, D=256 ----------------
// smem offsets (bytes)
#define AQH 0
#define AQL 32768
#define AKH 65536
#define AKL 98304
#define AVH 131072
#define AVL 163840
#define ASS 196608
#define SSS 68
#define APH (ASS + 64*SSS*4)       // 214016
#define APL (APH + 8192)            // 222208
#define AMR (APL + 8192)            // 230400
#define ALR (AMR + 256)             // 230656
#define ACR (ALR + 256)             // 230912
#define ATT_SMEM (ACR + 256)        // 231168

__device__ __forceinline__ uint32_t sw512(int row, int g) {
    return (uint32_t)(row * 512 + ((g ^ (row & 7)) << 4));
}
__device__ __forceinline__ uint32_t sw128(int row, int g) {
    return (uint32_t)(row * 128 + ((g ^ (row & 7)) << 4));
}

__global__ __launch_bounds__(256, 1) void attn_mma_kernel()
{
    extern __shared__ char sm[];
    const uint32_t sb = smem_to_u32(sm);
    const int tid  = threadIdx.x;
    const int lane = tid & 31;
    const int wid  = tid >> 5;
    const int qt   = gridDim.x - 1 - blockIdx.x;   // big tiles first
    const int h    = blockIdx.y;
    const int g    = h >> 2;
    const int i0   = qt * 64;

    float* Ss   = reinterpret_cast<float*>(sm + ASS);
    float* mrow = reinterpret_cast<float*>(sm + AMR);
    float* lrow = reinterpret_cast<float*>(sm + ALR);
    float* crow = reinterpret_cast<float*>(sm + ACR);

    // ---- Q hi/lo load (once) ----
    {
        const char* qh = (const char*)(g_qh + ((size_t)i0 * NHEADS + h) * HDIM);
        const char* ql = (const char*)(g_ql + ((size_t)i0 * NHEADS + h) * HDIM);
        const size_t rstr = (size_t)NHEADS * HDIM * 2;   // bytes per q-row
#pragma unroll
        for (int i = 0; i < 8; i++) {
            int idx = tid + 256 * i;           // 0..2047
            int row = idx >> 5, gr = idx & 31;
            uint32_t so = sw512(row, gr);
            cp_async16(sb + AQH + so, qh + (size_t)row * rstr + gr * 16);
            cp_async16(sb + AQL + so, ql + (size_t)row * rstr + gr * 16);
        }
    }
    CP_COMMIT();
    if (tid < 64) { mrow[tid] = -INFINITY; lrow[tid] = 0.0f; }

    const int wm = wid & 3;        // m-group (16 rows)
    const int wn = wid >> 2;       // n-group: S=32 cols, PV=128 cols
    const int er = lane >> 2;
    const int ec = (lane & 3) * 2;
    const int kgl = lane >> 4;

    float oacc[16][4];
#pragma unroll
    for (int t = 0; t < 16; t++)
#pragma unroll
        for (int r = 0; r < 4; r++) oacc[t][r] = 0.0f;

    CP_WAIT0();
    __syncthreads();

    for (int j0 = 0; j0 <= i0; j0 += 64) {
        // ---- load K/V hi/lo tile ----
        {
            const size_t rbase = ((size_t)j0 * NGROUPS + g) * HDIM;
            const size_t rstr  = (size_t)NGROUPS * HDIM;        // elems
#pragma unroll
            for (int i = 0; i < 8; i++) {
                int idx = tid + 256 * i;
                int row = idx >> 5, gr = idx & 31;
                size_t go = (rbase + (size_t)row * rstr) * 2 + gr * 16;
                uint32_t so = sw512(row, gr);
                cp_async16(sb + AKH + so, (const char*)g_kh + go);
                cp_async16(sb + AKL + so, (const char*)g_kl + go);
                cp_async16(sb + AVH + so, (const char*)g_vh + go);
                cp_async16(sb + AVL + so, (const char*)g_vl + go);
            }
        }
        CP_COMMIT(); CP_WAIT0();
        __syncthreads();

        // ---- S = Q K^T (3-term split) ----
        float sacc[4][4];
#pragma unroll
        for (int t = 0; t < 4; t++)
#pragma unroll
            for (int r = 0; r < 4; r++) sacc[t][r] = 0.0f;

        const int arow  = wm * 16 + (lane & 15);
        const int brow0 = wn * 32 + (lane & 15);
#pragma unroll 4
        for (int ks = 0; ks < 16; ks++) {
            int kg = ks * 2 + kgl;
            uint32_t ah[4], al[4], bh[2][4], bl[2][4];
            uint32_t ao = sw512(arow, kg);
            ldsm_x4(ah, sb + AQH + ao);
            ldsm_x4(al, sb + AQL + ao);
            uint32_t bo0 = sw512(brow0, kg);
            uint32_t bo1 = sw512(brow0 + 16, kg);
            ldsm_x4(bh[0], sb + AKH + bo0);
            ldsm_x4(bh[1], sb + AKH + bo1);
            ldsm_x4(bl[0], sb + AKL + bo0);
            ldsm_x4(bl[1], sb + AKL + bo1);
#pragma unroll
            for (int nt = 0; nt < 2; nt++)
#pragma unroll
                for (int sub = 0; sub < 2; sub++) {
                    float* d = sacc[nt * 2 + sub];
                    mma16816(d, ah, bh[nt][sub], bh[nt][2 + sub]);
                    mma16816(d, ah, bl[nt][sub], bl[nt][2 + sub]);
                    mma16816(d, al, bh[nt][sub], bh[nt][2 + sub]);
                }
        }
#pragma unroll
        for (int t = 0; t < 4; t++) {
            int col = wn * 32 + (t >> 1) * 16 + (t & 1) * 8 + ec;
            int r0 = wm * 16 + er;
            Ss[r0 * SSS + col]           = sacc[t][0];
            Ss[r0 * SSS + col + 1]       = sacc[t][1];
            Ss[(r0 + 8) * SSS + col]     = sacc[t][2];
            Ss[(r0 + 8) * SSS + col + 1] = sacc[t][3];
        }
        __syncthreads();

        // ---- online softmax + P hi/lo conversion (4 threads / row) ----
        {
            const int row  = tid >> 2;
            const int part = tid & 3;
            int vlim = i0 + row - j0 + 1; if (vlim > 64) vlim = 64;
            float sv[16];
            float mx = -INFINITY;
            const float* srow = &Ss[row * SSS + part * 16];
#pragma unroll
            for (int c = 0; c < 16; c++) {
                int cc = part * 16 + c;
                float v = (cc < vlim) ? srow[c] : -INFINITY;
                sv[c] = v; mx = fmaxf(mx, v);
            }
            mx = fmaxf(mx, __shfl_xor_sync(0xffffffffu, mx, 1));
            mx = fmaxf(mx, __shfl_xor_sync(0xffffffffu, mx, 2));
            float mold = mrow[row];
            float mnew = fmaxf(mold, mx);
            float ls = 0.0f;
#pragma unroll
            for (int c = 0; c < 16; c++) {
                float p = __expf(sv[c] - mnew);
                sv[c] = p; ls += p;
            }
            ls += __shfl_xor_sync(0xffffffffu, ls, 1);
            ls += __shfl_xor_sync(0xffffffffu, ls, 2);
            float corr = __expf(mold - mnew);
            if (part == 0) {
                mrow[row] = mnew;
                lrow[row] = lrow[row] * corr + ls;
                crow[row] = corr;
            }
#pragma unroll
            for (int gs = 0; gs < 2; gs++) {
                uint32_t hw[4], lw[4];
#pragma unroll
                for (int q = 0; q < 4; q++) {
                    float p0 = sv[gs * 8 + q * 2], p1 = sv[gs * 8 + q * 2 + 1];
                    __nv_bfloat16 h0 = __float2bfloat16(p0);
                    __nv_bfloat16 h1 = __float2bfloat16(p1);
                    __nv_bfloat16 l0 = __float2bfloat16(p0 - __bfloat162float(h0));
                    __nv_bfloat16 l1 = __float2bfloat16(p1 - __bfloat162float(h1));
                    hw[q] = pack_bf16x2(h0, h1);
                    lw[q] = pack_bf16x2(l0, l1);
                }
                uint32_t off = sw128(row, part * 2 + gs);
                *reinterpret_cast<uint4*>(sm + APH + off) = make_uint4(hw[0], hw[1], hw[2], hw[3]);
                *reinterpret_cast<uint4*>(sm + APL + off) = make_uint4(lw[0], lw[1], lw[2], lw[3]);
            }
        }
        __syncthreads();

        // ---- rescale O, then O += P V (3-term split) ----
        {
            float c0 = crow[wm * 16 + er];
            float c1 = crow[wm * 16 + er + 8];
#pragma unroll
            for (int t = 0; t < 16; t++) {
                oacc[t][0] *= c0; oacc[t][1] *= c0;
                oacc[t][2] *= c1; oacc[t][3] *= c1;
            }
        }
        const int prow = wm * 16 + (lane & 15);
        const int vk   = lane & 15;
        const int vng  = lane >> 4;
#pragma unroll
        for (int ks = 0; ks < 4; ks++) {
            uint32_t ah[4], al[4];
            uint32_t po = sw128(prow, ks * 2 + kgl);
            ldsm_x4(ah, sb + APH + po);
            ldsm_x4(al, sb + APL + po);
            int krow = ks * 16 + vk;
#pragma unroll
            for (int ng = 0; ng < 8; ng++) {
                uint32_t vh[4], vl[4];
                int gv = wn * 16 + ng * 2 + vng;
                uint32_t vo = sw512(krow, gv);
                ldsm_x4_trans(vh, sb + AVH + vo);
                ldsm_x4_trans(vl, sb + AVL + vo);
#pragma unroll
                for (int sub = 0; sub < 2; sub++) {
                    float* d = oacc[ng * 2 + sub];
                    mma16816(d, ah, vh[2 * sub], vh[2 * sub + 1]);
                    mma16816(d, ah, vl[2 * sub], vl[2 * sub + 1]);
                    mma16816(d, al, vh[2 * sub], vh[2 * sub + 1]);
                }
            }
        }
        __syncthreads();
    }

    // ---- epilogue: 1/l, sigmoid gate, write hi/lo bf16 ----
    {
        const int r0 = wm * 16 + er;
        const float li0 = 1.0f / lrow[r0];
        const float li1 = 1.0f / lrow[r0 + 8];
        const size_t base0 = (size_t)(i0 + r0) * ODIM + h * HDIM;
        const size_t base1 = (size_t)(i0 + r0 + 8) * ODIM + h * HDIM;
#pragma unroll
        for (int t = 0; t < 16; t++) {
            int col = wn * 128 + (t >> 1) * 16 + (t & 1) * 8 + ec;
            float2 gt0 = *reinterpret_cast<const float2*>(&g_gate[base0 + col]);
            float2 gt1 = *reinterpret_cast<const float2*>(&g_gate[base1 + col]);
            float v00 = oacc[t][0] * li0 * (1.0f / (1.0f + __expf(-gt0.x)));
            float v01 = oacc[t][1] * li0 * (1.0f / (1.0f + __expf(-gt0.y)));
            float v10 = oacc[t][2] * li1 * (1.0f / (1.0f + __expf(-gt1.x)));
            float v11 = oacc[t][3] * li1 * (1.0f / (1.0f + __expf(-gt1.y)));
            __nv_bfloat16 h00 = __float2bfloat16(v00), h01 = __float2bfloat16(v01);
            __nv_bfloat16 h10 = __float2bfloat16(v10), h11 = __float2bfloat16(v11);
            __nv_bfloat16 l00 = __float2bfloat16(v00 - __bfloat162float(h00));
            __nv_bfloat16 l01 = __float2bfloat16(v01 - __bfloat162float(h01));
            __nv_bfloat16 l10 = __float2bfloat16(v10 - __bfloat162float(h10));
            __nv_bfloat16 l11 = __float2bfloat16(v11 - __bfloat162float(h11));
            *reinterpret_cast<uint32_t*>(&g_ath[base0 + col]) = pack_bf16x2(h00, h01);
            *reinterpret_cast<uint32_t*>(&g_atl[base0 + col]) = pack_bf16x2(l00, l01);
            *reinterpret_cast<uint32_t*>(&g_ath[base1 + col]) = pack_bf16x2(h10, h11);
            *reinterpret_cast<uint32_t*>(&g_atl[base1 + col]) = pack_bf16x2(l10, l11);
        }
    }
}

// ---------------- launch ----------------
extern "C" void kernel_launch(void* const* d_in, const int* in_sizes, int n_in,
                              void* d_out, int out_size)
{
    const float* x    = (const float*)d_in[0];
    const float* cosb = (const float*)d_in[1];
    const float* sinb = (const float*)d_in[2];
    const float* wq   = (const float*)d_in[4];
    const float* wk   = (const float*)d_in[5];
    const float* wv   = (const float*)d_in[6];
    const float* wo   = (const float*)d_in[7];
    const float* qg   = (const float*)d_in[8];
    const float* kg   = (const float*)d_in[9];
    float* out        = (float*)d_out;

    float *p_qraw, *p_kraw, *p_v;
    cudaGetSymbolAddress((void**)&p_qraw, g_qraw);
    cudaGetSymbolAddress((void**)&p_kraw, g_kraw);
    cudaGetSymbolAddress((void**)&p_v,    g_v);

    __nv_bfloat16 *p_xh, *p_xl, *p_wqh, *p_wql, *p_wkh, *p_wkl, *p_wvh, *p_wvl,
                  *p_woh, *p_wol, *p_ath, *p_atl, *p_vh, *p_vl;
    cudaGetSymbolAddress((void**)&p_xh,  g_xh);
    cudaGetSymbolAddress((void**)&p_xl,  g_xl);
    cudaGetSymbolAddress((void**)&p_wqh, g_wqh);
    cudaGetSymbolAddress((void**)&p_wql, g_wql);
    cudaGetSymbolAddress((void**)&p_wkh, g_wkh);
    cudaGetSymbolAddress((void**)&p_wkl, g_wkl);
    cudaGetSymbolAddress((void**)&p_wvh, g_wvh);
    cudaGetSymbolAddress((void**)&p_wvl, g_wvl);
    cudaGetSymbolAddress((void**)&p_woh, g_woh);
    cudaGetSymbolAddress((void**)&p_wol, g_wol);
    cudaGetSymbolAddress((void**)&p_ath, g_ath);
    cudaGetSymbolAddress((void**)&p_atl, g_atl);
    cudaGetSymbolAddress((void**)&p_vh,  g_vh);
    cudaGetSymbolAddress((void**)&p_vl,  g_vl);

    const int gemm_smem = 2 * STAGE_BYTES;   // 81920
    cudaFuncSetAttribute(mma_gemm, cudaFuncAttributeMaxDynamicSharedMemorySize, gemm_smem);
    cudaFuncSetAttribute(attn_mma_kernel, cudaFuncAttributeMaxDynamicSharedMemorySize, ATT_SMEM);

    // 0) operand prep
    split_kernel<<<1024, 256>>>(x, p_xh, p_xl, (size_t)L_SEQ * IDIM / 4);
    transpose_split_kernel<<<dim3((ODIM*2)/32, IDIM/32), 256>>>(wq, p_wqh, p_wql, IDIM, ODIM*2);
    transpose_split_kernel<<<dim3(NKV/32,      IDIM/32), 256>>>(wk, p_wkh, p_wkl, IDIM, NKV);
    transpose_split_kernel<<<dim3(NKV/32,      IDIM/32), 256>>>(wv, p_wvh, p_wvl, IDIM, NKV);
    transpose_split_kernel<<<dim3(IDIM/32,     ODIM/32), 256>>>(wo, p_woh, p_wol, ODIM, IDIM);

    // 1) projections
    mma_gemm<<<dim3((ODIM*2)/128, L_SEQ/128), 256, gemm_smem>>>(p_xh, p_xl, p_wqh, p_wql, p_qraw, ODIM*2);
    mma_gemm<<<dim3(NKV/128,      L_SEQ/128), 256, gemm_smem>>>(p_xh, p_xl, p_wkh, p_wkl, p_kraw, NKV);
    mma_gemm<<<dim3(NKV/128,      L_SEQ/128), 256, gemm_smem>>>(p_xh, p_xl, p_wvh, p_wvl, p_v,    NKV);

    // 2) norms + RoPE -> bf16 hi/lo; V split
    qnorm_rope_kernel<<<dim3(L_SEQ, NHEADS),  256>>>(cosb, sinb, qg);
    knorm_rope_kernel<<<dim3(L_SEQ, NGROUPS), 256>>>(cosb, sinb, kg);
    split_kernel<<<512, 256>>>(p_v, p_vh, p_vl, (size_t)L_SEQ * NKV / 4);

    // 3) MMA flash attention + gating -> hi/lo bf16
    attn_mma_kernel<<<dim3(L_SEQ / 64, NHEADS), 256, ATT_SMEM>>>();

    // 4) output projection
    mma_gemm<<<dim3(IDIM/128, L_SEQ/128), 256, gemm_smem>>>(p_ath, p_atl, p_woh, p_wol, out, IDIM);
}